// round 10
// baseline (speedup 1.0000x reference)
#include <cuda_runtime.h>
#include <cuda_fp16.h>
#include <cstdint>

#define BSZ   256
#define MM    128
#define NN    1024
#define ITERS 100
#define ALPHA 0.1f

__device__ __half g_Ah[(size_t)BSZ * MM * NN];
__device__ float  g_C [(size_t)BSZ * MM * MM];   // AAT -> inverse (in place)

__device__ __forceinline__ uint32_t smem_u32(const void* p) {
    uint32_t a;
    asm("{ .reg .u64 t; cvta.to.shared.u64 t, %1; cvt.u32.u64 %0, t; }" : "=r"(a) : "l"(p));
    return a;
}
__device__ __forceinline__ uint32_t mapa_rank(uint32_t addr, uint32_t trank) {
    uint32_t r;
    asm("mapa.shared::cluster.u32 %0, %1, %2;" : "=r"(r) : "r"(addr), "r"(trank));
    return r;
}
__device__ __forceinline__ void cluster_sync_() {
    asm volatile("barrier.cluster.arrive.aligned;" ::: "memory");
    asm volatile("barrier.cluster.wait.aligned;"   ::: "memory");
}
__device__ __forceinline__ void st_cluster_f32(uint32_t addr, float v) {
    asm volatile("st.shared::cluster.f32 [%0], %1;" :: "r"(addr), "f"(v) : "memory");
}
__device__ __forceinline__ void mbar_init(uint32_t a, uint32_t c) {
    asm volatile("mbarrier.init.shared.b64 [%0], %1;" :: "r"(a), "r"(c) : "memory");
}
__device__ __forceinline__ void mbar_arrive_remote(uint32_t ra) {
    asm volatile("mbarrier.arrive.release.cluster.shared::cluster.b64 _, [%0];" :: "r"(ra) : "memory");
}
__device__ __forceinline__ void mbar_wait_acq(uint32_t mb, uint32_t par) {
    asm volatile(
        "{\n\t.reg .pred P;\n\t"
        "WL%=:\n\t"
        "mbarrier.try_wait.parity.acquire.cluster.shared::cta.b64 P, [%0], %1, 0x989680;\n\t"
        "@P bra.uni WD%=;\n\t"
        "bra.uni WL%=;\n\t"
        "WD%=:\n\t}" :: "r"(mb), "r"(par) : "memory");
}
__device__ __forceinline__ void ldsm_x4(uint32_t& a0, uint32_t& a1, uint32_t& a2, uint32_t& a3, uint32_t addr) {
    asm volatile("ldmatrix.sync.aligned.m8n8.x4.shared.b16 {%0,%1,%2,%3}, [%4];"
                 : "=r"(a0), "=r"(a1), "=r"(a2), "=r"(a3) : "r"(addr));
}
__device__ __forceinline__ void ldsm_x4t(uint32_t& a0, uint32_t& a1, uint32_t& a2, uint32_t& a3, uint32_t addr) {
    asm volatile("ldmatrix.sync.aligned.m8n8.x4.trans.shared.b16 {%0,%1,%2,%3}, [%4];"
                 : "=r"(a0), "=r"(a1), "=r"(a2), "=r"(a3) : "r"(addr));
}
__device__ __forceinline__ void mma16816(float& c0, float& c1, float& c2, float& c3,
                                         uint32_t a0, uint32_t a1, uint32_t a2, uint32_t a3,
                                         uint32_t b0, uint32_t b1) {
    asm volatile("mma.sync.aligned.m16n8k16.row.col.f32.f16.f16.f32 "
                 "{%0,%1,%2,%3},{%4,%5,%6,%7},{%8,%9},{%0,%1,%2,%3};"
                 : "+f"(c0), "+f"(c1), "+f"(c2), "+f"(c3)
                 : "r"(a0), "r"(a1), "r"(a2), "r"(a3), "r"(b0), "r"(b1));
}

// --------------------------------------------------------------------------
__global__ void k_convert(const float* __restrict__ A) {
    size_t i = ((size_t)blockIdx.x * blockDim.x + threadIdx.x) * 4;
    float4 v = *(const float4*)(A + i);
    __half2* dst = (__half2*)(g_Ah + i);
    dst[0] = __floats2half2_rn(v.x, v.y);
    dst[1] = __floats2half2_rn(v.z, v.w);
}

// k_aat (HMMA, verified R9) --------------------------------------------------
#define AT_PITCH_B 272
__global__ void __launch_bounds__(256) k_aat() {
    __shared__ __half tile[128 * (AT_PITCH_B / 2)];
    const int b = blockIdx.x, t = threadIdx.x, w = t >> 5, l = t & 31;
    const __half* Ab = g_Ah + (size_t)b * MM * NN;
    const uint32_t tbase = smem_u32(tile);

    float acc[16][4];
#pragma unroll
    for (int nt = 0; nt < 16; nt++)
#pragma unroll
        for (int q = 0; q < 4; q++) acc[nt][q] = 0.0f;

    const int m0 = w * 16;
    const uint32_t aAddr = tbase + (uint32_t)(m0 + (l & 15)) * AT_PITCH_B
                         + (uint32_t)((l >> 4) << 4);
    const int bg = l >> 3;
    const uint32_t bAddr0 = tbase + (uint32_t)((l & 7) + ((bg >> 1) << 3)) * AT_PITCH_B
                          + (uint32_t)((bg & 1) << 4);

    for (int kc = 0; kc < 8; kc++) {
#pragma unroll
        for (int q = 0; q < 8; q++) {
            int i = t + 256 * q, r = i >> 4, c4 = i & 15;
            *(uint4*)((char*)tile + r * AT_PITCH_B + c4 * 16) =
                *(const uint4*)(Ab + (size_t)r * NN + kc * 128 + c4 * 8);
        }
        __syncthreads();

#pragma unroll
        for (int kt = 0; kt < 8; kt++) {
            uint32_t a0, a1, a2, a3;
            ldsm_x4(a0, a1, a2, a3, aAddr + (uint32_t)(kt * 32));
#pragma unroll
            for (int nt = 0; nt < 16; nt += 2) {
                uint32_t r0, r1, r2, r3;
                ldsm_x4(r0, r1, r2, r3,
                        bAddr0 + (uint32_t)(nt * 8) * AT_PITCH_B + (uint32_t)(kt * 32));
                mma16816(acc[nt][0],   acc[nt][1],   acc[nt][2],   acc[nt][3],
                         a0, a1, a2, a3, r0, r1);
                mma16816(acc[nt+1][0], acc[nt+1][1], acc[nt+1][2], acc[nt+1][3],
                         a0, a1, a2, a3, r2, r3);
            }
        }
        __syncthreads();
    }

    float* Cb = g_C + (size_t)b * MM * MM;
    const int r0 = m0 + (l >> 2), c0 = 2 * (l & 3);
#pragma unroll
    for (int nt = 0; nt < 16; nt++) {
        *(float2*)&Cb[(size_t)r0 * MM + nt * 8 + c0]       = make_float2(acc[nt][0], acc[nt][1]);
        *(float2*)&Cb[(size_t)(r0 + 8) * MM + nt * 8 + c0] = make_float2(acc[nt][2], acc[nt][3]);
    }
}

// Gauss-Jordan inverse, 512 threads ------------------------------------------
__global__ void __launch_bounds__(512) k_inv() {
    extern __shared__ float sm[];
    float* sM = sm; float* sf = sm + 16384; float* sp = sm + 16512;
    int b = blockIdx.x, t = threadIdx.x;
    float* Cb = g_C + (size_t)b * MM * MM;
    for (int i = t; i < 4096; i += 512) ((float4*)sM)[i] = ((const float4*)Cb)[i];
    __syncthreads();
    for (int k = 0; k < 128; k++) {
        if (t == 0) sp[0] = 1.0f / sM[k * 128 + k];
        __syncthreads();
        float ipiv = sp[0];
        if (t < 128) {
            float v = sM[k * 128 + t];
            sM[k * 128 + t] = (t == k) ? ipiv : v * ipiv;
            sf[t] = (t == k) ? 0.0f : sM[t * 128 + k];
        }
        __syncthreads();
        int j = t & 127, g = t >> 7;
        float mk = sM[k * 128 + j];
#pragma unroll 4
        for (int ii = 0; ii < 32; ii++) {
            int i = g * 32 + ii;
            if (i == k) continue;
            float fi = sf[i];
            float v = sM[i * 128 + j];
            sM[i * 128 + j] = (j == k) ? (-fi * mk) : (v - fi * mk);
        }
        __syncthreads();
    }
    for (int i = t; i < 4096; i += 512) ((float4*)Cb)[i] = ((const float4*)sM)[i];
}

// Iterations: R6 core + early push + split accumulators + 512-thread u-stage --
#define APAD_U4  65
#define OFF_C    0                     // 16384 f
#define OFF_A    16384                 // 33280 w
#define OFF_YH   49664                 // 256 u32
#define OFF_YL   49920                 // 256 u32
#define OFF_B    50176                 // 128 f
#define OFF_SR0  50304                 // 128 f
#define OFF_SR1  50432                 // 128 f
#define OFF_REM  50560                 // 512 f : [buf][kh][128]
#define OFF_RT   51072                 // 128 f
#define OFF_UH   51200                 // 64 u32
#define OFF_UL   51264                 // 64 u32
#define OFF_CORR 51328                 // 512 f
#define OFF_MB   51840                 // 2 x u64
#define SMEM_WORDS 51844               // 207376 bytes

__global__ void __launch_bounds__(512, 1) __cluster_dims__(2, 1, 1)
k_iter(const float* __restrict__ bvec, const float* __restrict__ D1,
       const float* __restrict__ D2, float* __restrict__ out) {
    extern __shared__ float sm[];
    const int t = threadIdx.x, w = t >> 5, l = t & 31;
    const int b = blockIdx.x >> 1;
    const uint32_t rank = blockIdx.x & 1;
    const uint32_t sbase = smem_u32(sm);
    const uint32_t peer = mapa_rank(sbase, rank ^ 1u);
    const uint32_t aA = sbase + OFF_A * 4u;

    {   // load C, padded A-half, b
        float4* d = (float4*)(sm + OFF_C);
        const float4* s = (const float4*)(g_C + (size_t)b * MM * MM);
#pragma unroll
        for (int q = 0; q < 8; q++) d[t + 512 * q] = s[t + 512 * q];
        uint4* da = (uint4*)(sm + OFF_A);
        const uint4* sa = (const uint4*)(g_Ah + (size_t)b * MM * NN + (size_t)rank * 512);
#pragma unroll
        for (int q = 0; q < 16; q++) {
            int i = t + 512 * q, r = i >> 6, c4 = i & 63;
            da[r * APAD_U4 + c4] = sa[(size_t)r * 128 + c4];
        }
        if (t < 128) sm[OFF_B + t] = bvec[(size_t)b * MM + t];
        if (t == 0) {
            mbar_init(sbase + OFF_MB * 4u, 128);
            mbar_init(sbase + OFF_MB * 4u + 8u, 128);
        }
    }

    float2 thr2 = make_float2(0.f, 0.f), dv2 = make_float2(0.f, 0.f);
    float2 z2 = make_float2(0.f, 0.f), xh2, yv2 = make_float2(0.f, 0.f);
    if (t < 256) {
        float2 d1 = ((const float2*)(D1 + (size_t)b * NN + rank * 512))[t];
        float2 d2 = ((const float2*)(D2 + (size_t)b * NN + rank * 512))[t];
        thr2.x = ALPHA * fabsf(d1.x); thr2.y = ALPHA * fabsf(d1.y);
        dv2.x = 1.0f / (1.0f + 2.0f * ALPHA * d2.x * d2.x);
        dv2.y = 1.0f / (1.0f + 2.0f * ALPHA * d2.y * d2.y);
    }
    __syncthreads();
    cluster_sync_();

    const int p1_m0 = (w & 7) * 16, p1_kh = w >> 3;
    const uint32_t p1_addr = aA + (uint32_t)(p1_m0 + (l & 15)) * 1040u
                           + (uint32_t)(p1_kh * 512) + (uint32_t)((l >> 4) << 4);
    const int bc = l & 3;
    const uint32_t p2_rowoff = (uint32_t)((l & 7) + ((l >> 4) << 3)) * 1040u
                             + (uint32_t)((l & 8) << 1);

    for (int it = 0; it < ITERS; it++) {
        const int buf = it & 1;
        // --- elementwise: soft-threshold, y = 2x_half - z, split to fp16 hi/lo
        if (t < 256) {
            float a0 = z2.x - thr2.x, c0 = z2.x + thr2.x;
            float a1 = z2.y - thr2.y, c1 = z2.y + thr2.y;
            xh2.x = (a0 > 0.f) ? a0 * dv2.x : ((c0 < 0.f) ? c0 * dv2.x : 0.f);
            xh2.y = (a1 > 0.f) ? a1 * dv2.y : ((c1 < 0.f) ? c1 * dv2.y : 0.f);
            yv2.x = 2.0f * xh2.x - z2.x;
            yv2.y = 2.0f * xh2.y - z2.y;
            __half2 hy = __floats2half2_rn(yv2.x, yv2.y);
            float2 fy = __half22float2(hy);
            __half2 ly = __floats2half2_rn(yv2.x - fy.x, yv2.y - fy.y);
            ((uint32_t*)(sm + OFF_YH))[t] = *(uint32_t*)&hy;
            ((uint32_t*)(sm + OFF_YL))[t] = *(uint32_t*)&ly;
        }
        __syncthreads();                                   // bar1: y ready

        // --- pass 1 (HMMA, split acc): partial r; early remote push ---
        {
            float ch0 = 0.f, ch1 = 0.f, ch2 = 0.f, ch3 = 0.f;
            float cl0 = 0.f, cl1 = 0.f, cl2 = 0.f, cl3 = 0.f;
            const uint32_t* yh = (const uint32_t*)(sm + OFF_YH) + p1_kh * 128;
            const uint32_t* yl = (const uint32_t*)(sm + OFF_YL) + p1_kh * 128;
            uint32_t addr = p1_addr;
#pragma unroll
            for (int kt = 0; kt < 16; kt++) {
                uint32_t a0, a1, a2, a3;
                ldsm_x4(a0, a1, a2, a3, addr);
                addr += 32u;
                int kb = kt * 8 + bc;
                mma16816(ch0, ch1, ch2, ch3, a0, a1, a2, a3, yh[kb], yh[kb + 4]);
                mma16816(cl0, cl1, cl2, cl3, a0, a1, a2, a3, yl[kb], yl[kb + 4]);
            }
            if ((l & 3) == 0) {
                float r0 = ch0 + cl0, r1 = ch2 + cl2;
                int row0 = p1_m0 + (l >> 2), row1 = row0 + 8;
                float* srp = sm + (p1_kh ? OFF_SR1 : OFF_SR0);
                srp[row0] = r0;
                srp[row1] = r1;
                // early push: my k-half partial into peer REM[buf][kh][row]
                uint32_t rb = peer + (uint32_t)(OFF_REM + buf * 256 + p1_kh * 128) * 4u;
                st_cluster_f32(rb + 4u * (uint32_t)row0, r0);
                st_cluster_f32(rb + 4u * (uint32_t)row1, r1);
                mbar_arrive_remote(peer + OFF_MB * 4u + 8u * buf);  // 128 arrivals total
            }
        }
        __syncthreads();                                   // bar2: local partials

        // --- rt (t<128): wait for peer's 128 arrivals, sum 4 partials - b ---
        if (t < 128) {
            mbar_wait_acq(sbase + OFF_MB * 4u + 8u * buf, (uint32_t)((it >> 1) & 1));
            sm[OFF_RT + t] = sm[OFF_SR0 + t] + sm[OFF_SR1 + t]
                           + sm[OFF_REM + buf * 256 + t]
                           + sm[OFF_REM + buf * 256 + 128 + t]
                           - sm[OFF_B + t];
        }
        __syncthreads();                                   // bar3: rt ready

        // --- u = C * rt (all 512 threads, 4/row, staggered), split hi/lo ---
        {
            int i = t >> 2, q = t & 3;
            float accu = 0.0f;
#pragma unroll
            for (int m = 0; m < 8; m++) {
                int j = q * 32 + 4 * (((i & 7) + m) & 7);
                float4 c4 = *(const float4*)(sm + OFF_C + i * 128 + j);
                float4 r4 = *(const float4*)(sm + OFF_RT + j);
                accu += c4.x * r4.x + c4.y * r4.y + c4.z * r4.z + c4.w * r4.w;
            }
            accu += __shfl_xor_sync(0xffffffffu, accu, 1);
            accu += __shfl_xor_sync(0xffffffffu, accu, 2);
            float un = __shfl_down_sync(0xffffffffu, accu, 4);
            if ((t & 7) == 0) {
                __half2 hu = __floats2half2_rn(accu, un);
                float2 fu = __half22float2(hu);
                __half2 lu = __floats2half2_rn(accu - fu.x, un - fu.y);
                ((uint32_t*)(sm + OFF_UH))[t >> 3] = *(uint32_t*)&hu;
                ((uint32_t*)(sm + OFF_UL))[t >> 3] = *(uint32_t*)&lu;
            }
        }
        __syncthreads();                                   // bar4: u ready

        // --- pass 2 (HMMA trans, split acc): corr = A^T * u ---
        {
            const uint32_t* uh = (const uint32_t*)(sm + OFF_UH);
            const uint32_t* ul = (const uint32_t*)(sm + OFF_UL);
#pragma unroll
            for (int mi = 0; mi < 2; mi++) {
                int mt = 2 * w + mi, cc0 = mt * 16;
                float dh0 = 0.f, dh1 = 0.f, dh2 = 0.f, dh3 = 0.f;
                float dl0 = 0.f, dl1 = 0.f, dl2 = 0.f, dl3 = 0.f;
                uint32_t addr = aA + p2_rowoff + (uint32_t)(cc0 * 2);
#pragma unroll
                for (int kt = 0; kt < 8; kt++) {
                    uint32_t a0, a1, a2, a3;
                    ldsm_x4t(a0, a1, a2, a3, addr);
                    addr += 16u * 1040u;
                    int kb = kt * 8 + bc;
                    mma16816(dh0, dh1, dh2, dh3, a0, a1, a2, a3, uh[kb], uh[kb + 4]);
                    mma16816(dl0, dl1, dl2, dl3, a0, a1, a2, a3, ul[kb], ul[kb + 4]);
                }
                if ((l & 3) == 0) {
                    sm[OFF_CORR + cc0 + (l >> 2)]     = dh0 + dl0;
                    sm[OFF_CORR + cc0 + 8 + (l >> 2)] = dh2 + dl2;
                }
            }
        }
        __syncthreads();                                   // bar5: corr ready

        // --- epilogue ---
        if (t < 256) {
            float2 cr = *(const float2*)(sm + OFF_CORR + 2 * t);
            z2.x = xh2.x - cr.x; z2.y = xh2.y - cr.y;
            yv2.x -= cr.x; yv2.y -= cr.y;                  // x_new
        }
    }

    if (t < 256)
        ((float2*)(out + (size_t)b * NN + rank * 512))[t] = yv2;
    cluster_sync_();
}

// --------------------------------------------------------------------------
extern "C" void kernel_launch(void* const* d_in, const int* in_sizes, int n_in,
                              void* d_out, int out_size) {
    const float* A  = (const float*)d_in[0];
    const float* bv = (const float*)d_in[1];
    const float* D1 = (const float*)d_in[2];
    const float* D2 = (const float*)d_in[3];
    float* out = (float*)d_out;

    cudaFuncSetAttribute(k_inv,  cudaFuncAttributeMaxDynamicSharedMemorySize, 66052);
    cudaFuncSetAttribute(k_iter, cudaFuncAttributeMaxDynamicSharedMemorySize, SMEM_WORDS * 4);

    k_convert<<<32768, 256>>>(A);
    k_aat<<<BSZ, 256>>>();
    k_inv<<<BSZ, 512, 66052>>>();
    k_iter<<<BSZ * 2, 512, SMEM_WORDS * 4>>>(bv, D1, D2, out);
}

// round 11
// speedup vs baseline: 1.3806x; 1.3806x over previous
#include <cuda_runtime.h>
#include <cuda_fp16.h>
#include <cstdint>

#define BSZ   256
#define MM    128
#define NN    1024
#define ITERS 100
#define ALPHA 0.1f

__device__ __half g_Ah[(size_t)BSZ * MM * NN];
__device__ float  g_C [(size_t)BSZ * MM * MM];   // AAT -> inverse (in place)

__device__ __forceinline__ uint32_t smem_u32(const void* p) {
    uint32_t a;
    asm("{ .reg .u64 t; cvta.to.shared.u64 t, %1; cvt.u32.u64 %0, t; }" : "=r"(a) : "l"(p));
    return a;
}
__device__ __forceinline__ uint32_t mapa_rank(uint32_t addr, uint32_t trank) {
    uint32_t r;
    asm("mapa.shared::cluster.u32 %0, %1, %2;" : "=r"(r) : "r"(addr), "r"(trank));
    return r;
}
__device__ __forceinline__ void cluster_sync_() {
    asm volatile("barrier.cluster.arrive.aligned;" ::: "memory");
    asm volatile("barrier.cluster.wait.aligned;"   ::: "memory");
}
__device__ __forceinline__ void st_cluster_f32(uint32_t addr, float v) {
    asm volatile("st.shared::cluster.f32 [%0], %1;" :: "r"(addr), "f"(v) : "memory");
}
__device__ __forceinline__ void mbar_init(uint32_t a, uint32_t c) {
    asm volatile("mbarrier.init.shared.b64 [%0], %1;" :: "r"(a), "r"(c) : "memory");
}
__device__ __forceinline__ void mbar_arrive_remote(uint32_t ra) {
    asm volatile("mbarrier.arrive.release.cluster.shared::cluster.b64 _, [%0];" :: "r"(ra) : "memory");
}
__device__ __forceinline__ void mbar_wait_acq(uint32_t mb, uint32_t par) {
    asm volatile(
        "{\n\t.reg .pred P;\n\t"
        "WL%=:\n\t"
        "mbarrier.try_wait.parity.acquire.cluster.shared::cta.b64 P, [%0], %1, 0x989680;\n\t"
        "@P bra.uni WD%=;\n\t"
        "bra.uni WL%=;\n\t"
        "WD%=:\n\t}" :: "r"(mb), "r"(par) : "memory");
}
__device__ __forceinline__ void ldsm_x4(uint32_t& a0, uint32_t& a1, uint32_t& a2, uint32_t& a3, uint32_t addr) {
    asm volatile("ldmatrix.sync.aligned.m8n8.x4.shared.b16 {%0,%1,%2,%3}, [%4];"
                 : "=r"(a0), "=r"(a1), "=r"(a2), "=r"(a3) : "r"(addr));
}
__device__ __forceinline__ void ldsm_x4t(uint32_t& a0, uint32_t& a1, uint32_t& a2, uint32_t& a3, uint32_t addr) {
    asm volatile("ldmatrix.sync.aligned.m8n8.x4.trans.shared.b16 {%0,%1,%2,%3}, [%4];"
                 : "=r"(a0), "=r"(a1), "=r"(a2), "=r"(a3) : "r"(addr));
}
__device__ __forceinline__ void mma16816(float& c0, float& c1, float& c2, float& c3,
                                         uint32_t a0, uint32_t a1, uint32_t a2, uint32_t a3,
                                         uint32_t b0, uint32_t b1) {
    asm volatile("mma.sync.aligned.m16n8k16.row.col.f32.f16.f16.f32 "
                 "{%0,%1,%2,%3},{%4,%5,%6,%7},{%8,%9},{%0,%1,%2,%3};"
                 : "+f"(c0), "+f"(c1), "+f"(c2), "+f"(c3)
                 : "r"(a0), "r"(a1), "r"(a2), "r"(a3), "r"(b0), "r"(b1));
}

// --------------------------------------------------------------------------
__global__ void k_convert(const float* __restrict__ A) {
    size_t i = ((size_t)blockIdx.x * blockDim.x + threadIdx.x) * 4;
    float4 v = *(const float4*)(A + i);
    __half2* dst = (__half2*)(g_Ah + i);
    dst[0] = __floats2half2_rn(v.x, v.y);
    dst[1] = __floats2half2_rn(v.z, v.w);
}

// k_aat (HMMA, verified R9) --------------------------------------------------
#define AT_PITCH_B 272
__global__ void __launch_bounds__(256) k_aat() {
    __shared__ __half tile[128 * (AT_PITCH_B / 2)];
    const int b = blockIdx.x, t = threadIdx.x, w = t >> 5, l = t & 31;
    const __half* Ab = g_Ah + (size_t)b * MM * NN;
    const uint32_t tbase = smem_u32(tile);

    float acc[16][4];
#pragma unroll
    for (int nt = 0; nt < 16; nt++)
#pragma unroll
        for (int q = 0; q < 4; q++) acc[nt][q] = 0.0f;

    const int m0 = w * 16;
    const uint32_t aAddr = tbase + (uint32_t)(m0 + (l & 15)) * AT_PITCH_B
                         + (uint32_t)((l >> 4) << 4);
    const int bg = l >> 3;
    const uint32_t bAddr0 = tbase + (uint32_t)((l & 7) + ((bg >> 1) << 3)) * AT_PITCH_B
                          + (uint32_t)((bg & 1) << 4);

    for (int kc = 0; kc < 8; kc++) {
#pragma unroll
        for (int q = 0; q < 8; q++) {
            int i = t + 256 * q, r = i >> 4, c4 = i & 15;
            *(uint4*)((char*)tile + r * AT_PITCH_B + c4 * 16) =
                *(const uint4*)(Ab + (size_t)r * NN + kc * 128 + c4 * 8);
        }
        __syncthreads();

#pragma unroll
        for (int kt = 0; kt < 8; kt++) {
            uint32_t a0, a1, a2, a3;
            ldsm_x4(a0, a1, a2, a3, aAddr + (uint32_t)(kt * 32));
#pragma unroll
            for (int nt = 0; nt < 16; nt += 2) {
                uint32_t r0, r1, r2, r3;
                ldsm_x4(r0, r1, r2, r3,
                        bAddr0 + (uint32_t)(nt * 8) * AT_PITCH_B + (uint32_t)(kt * 32));
                mma16816(acc[nt][0],   acc[nt][1],   acc[nt][2],   acc[nt][3],
                         a0, a1, a2, a3, r0, r1);
                mma16816(acc[nt+1][0], acc[nt+1][1], acc[nt+1][2], acc[nt+1][3],
                         a0, a1, a2, a3, r2, r3);
            }
        }
        __syncthreads();
    }

    float* Cb = g_C + (size_t)b * MM * MM;
    const int r0 = m0 + (l >> 2), c0 = 2 * (l & 3);
#pragma unroll
    for (int nt = 0; nt < 16; nt++) {
        *(float2*)&Cb[(size_t)r0 * MM + nt * 8 + c0]       = make_float2(acc[nt][0], acc[nt][1]);
        *(float2*)&Cb[(size_t)(r0 + 8) * MM + nt * 8 + c0] = make_float2(acc[nt][2], acc[nt][3]);
    }
}

// Gauss-Jordan inverse, 512 threads (verified R10 setup win) -----------------
__global__ void __launch_bounds__(512) k_inv() {
    extern __shared__ float sm[];
    float* sM = sm; float* sf = sm + 16384; float* sp = sm + 16512;
    int b = blockIdx.x, t = threadIdx.x;
    float* Cb = g_C + (size_t)b * MM * MM;
    for (int i = t; i < 4096; i += 512) ((float4*)sM)[i] = ((const float4*)Cb)[i];
    __syncthreads();
    for (int k = 0; k < 128; k++) {
        if (t == 0) sp[0] = 1.0f / sM[k * 128 + k];
        __syncthreads();
        float ipiv = sp[0];
        if (t < 128) {
            float v = sM[k * 128 + t];
            sM[k * 128 + t] = (t == k) ? ipiv : v * ipiv;
            sf[t] = (t == k) ? 0.0f : sM[t * 128 + k];
        }
        __syncthreads();
        int j = t & 127, g = t >> 7;
        float mk = sM[k * 128 + j];
#pragma unroll 4
        for (int ii = 0; ii < 32; ii++) {
            int i = g * 32 + ii;
            if (i == k) continue;
            float fi = sf[i];
            float v = sM[i * 128 + j];
            sM[i * 128 + j] = (j == k) ? (-fi * mk) : (v - fi * mk);
        }
        __syncthreads();
    }
    for (int i = t; i < 4096; i += 512) ((float4*)Cb)[i] = ((const float4*)sM)[i];
}

// Iterations: EXACT R6/R9 winner (1361 us) -----------------------------------
#define APAD_U4  65
#define OFF_C    0                     // 16384 f
#define OFF_A    16384                 // 33280 w (128*260 u32)
#define OFF_YH   49664                 // 256 u32 (half2 y_hi)
#define OFF_YL   49920                 // 256 u32
#define OFF_B    50176                 // 128 f
#define OFF_SR0  50304                 // 128 f (khalf 0 partial)
#define OFF_SR1  50432                 // 128 f (khalf 1 partial)
#define OFF_REM  50560                 // 256 f (peer partial, 2 bufs)
#define OFF_RT   50816                 // 128 f
#define OFF_UH   50944                 // 64 u32 (half2 u_hi)
#define OFF_UL   51008                 // 64 u32
#define OFF_CORR 51072                 // 512 f
#define OFF_MB   51584                 // 2 x u64 mbarriers
#define SMEM_WORDS 51588               // 206352 bytes

__global__ void __launch_bounds__(512, 1) __cluster_dims__(2, 1, 1)
k_iter(const float* __restrict__ bvec, const float* __restrict__ D1,
       const float* __restrict__ D2, float* __restrict__ out) {
    extern __shared__ float sm[];
    const int t = threadIdx.x, w = t >> 5, l = t & 31;
    const int b = blockIdx.x >> 1;
    const uint32_t rank = blockIdx.x & 1;
    const uint32_t sbase = smem_u32(sm);
    const uint32_t peer = mapa_rank(sbase, rank ^ 1u);
    const uint32_t aA = sbase + OFF_A * 4u;

    {   // load C, padded A-half, b
        float4* d = (float4*)(sm + OFF_C);
        const float4* s = (const float4*)(g_C + (size_t)b * MM * MM);
#pragma unroll
        for (int q = 0; q < 8; q++) d[t + 512 * q] = s[t + 512 * q];
        uint4* da = (uint4*)(sm + OFF_A);
        const uint4* sa = (const uint4*)(g_Ah + (size_t)b * MM * NN + (size_t)rank * 512);
#pragma unroll
        for (int q = 0; q < 16; q++) {
            int i = t + 512 * q, r = i >> 6, c4 = i & 63;
            da[r * APAD_U4 + c4] = sa[(size_t)r * 128 + c4];
        }
        if (t < 128) sm[OFF_B + t] = bvec[(size_t)b * MM + t];
        if (t == 0) {
            mbar_init(sbase + OFF_MB * 4u, 128);
            mbar_init(sbase + OFF_MB * 4u + 8u, 128);
        }
    }

    // per-thread state: t<256 owns local cols 2t, 2t+1
    float2 thr2 = make_float2(0.f, 0.f), dv2 = make_float2(0.f, 0.f);
    float2 z2 = make_float2(0.f, 0.f), xh2, yv2 = make_float2(0.f, 0.f);
    if (t < 256) {
        float2 d1 = ((const float2*)(D1 + (size_t)b * NN + rank * 512))[t];
        float2 d2 = ((const float2*)(D2 + (size_t)b * NN + rank * 512))[t];
        thr2.x = ALPHA * fabsf(d1.x); thr2.y = ALPHA * fabsf(d1.y);
        dv2.x = 1.0f / (1.0f + 2.0f * ALPHA * d2.x * d2.x);
        dv2.y = 1.0f / (1.0f + 2.0f * ALPHA * d2.y * d2.y);
    }
    __syncthreads();
    cluster_sync_();

    // pass1 per-warp constants: warp w -> m-tile rows 16*(w&7), k-half w>>3
    const int p1_m0 = (w & 7) * 16, p1_kh = w >> 3;
    const uint32_t p1_addr = aA + (uint32_t)(p1_m0 + (l & 15)) * 1040u
                           + (uint32_t)(p1_kh * 512) + (uint32_t)((l >> 4) << 4);
    const int bc = l & 3;              // tid%4: b-frag k-subgroup
    // pass2: warp w -> m-tiles (cols) 2w, 2w+1
    const uint32_t p2_rowoff = (uint32_t)((l & 7) + ((l >> 4) << 3)) * 1040u
                             + (uint32_t)((l & 8) << 1);

    for (int it = 0; it < ITERS; it++) {
        const int buf = it & 1;
        // --- elementwise: soft-threshold, y = 2x_half - z, split to fp16 hi/lo
        if (t < 256) {
            float a0 = z2.x - thr2.x, c0 = z2.x + thr2.x;
            float a1 = z2.y - thr2.y, c1 = z2.y + thr2.y;
            xh2.x = (a0 > 0.f) ? a0 * dv2.x : ((c0 < 0.f) ? c0 * dv2.x : 0.f);
            xh2.y = (a1 > 0.f) ? a1 * dv2.y : ((c1 < 0.f) ? c1 * dv2.y : 0.f);
            yv2.x = 2.0f * xh2.x - z2.x;
            yv2.y = 2.0f * xh2.y - z2.y;
            __half2 hy = __floats2half2_rn(yv2.x, yv2.y);
            float2 fy = __half22float2(hy);
            __half2 ly = __floats2half2_rn(yv2.x - fy.x, yv2.y - fy.y);
            ((uint32_t*)(sm + OFF_YH))[t] = *(uint32_t*)&hy;
            ((uint32_t*)(sm + OFF_YL))[t] = *(uint32_t*)&ly;
        }
        __syncthreads();                                   // bar1: y ready

        // --- pass 1 (HMMA): r_partial[kh] = A[:, kh*256..] * y[kh half] ---
        {
            float c0 = 0.f, c1 = 0.f, c2 = 0.f, c3 = 0.f;
            const uint32_t* yh = (const uint32_t*)(sm + OFF_YH) + p1_kh * 128;
            const uint32_t* yl = (const uint32_t*)(sm + OFF_YL) + p1_kh * 128;
            uint32_t addr = p1_addr;
#pragma unroll
            for (int kt = 0; kt < 16; kt++) {
                uint32_t a0, a1, a2, a3;
                ldsm_x4(a0, a1, a2, a3, addr);
                addr += 32u;                                // +16 halves
                int kb = kt * 8 + bc;
                mma16816(c0, c1, c2, c3, a0, a1, a2, a3, yh[kb], yh[kb + 4]);
                mma16816(c0, c1, c2, c3, a0, a1, a2, a3, yl[kb], yl[kb + 4]);
            }
            if ((l & 3) == 0) {
                float* srp = sm + (p1_kh ? OFF_SR1 : OFF_SR0);
                srp[p1_m0 + (l >> 2)]     = c0;
                srp[p1_m0 + 8 + (l >> 2)] = c2;
            }
        }
        __syncthreads();                                   // bar2: partials ready

        // --- exchange + r_total (t<128) ---
        if (t < 128) {
            float s = sm[OFF_SR0 + t] + sm[OFF_SR1 + t];
            st_cluster_f32(peer + (uint32_t)(OFF_REM + buf * 128 + t) * 4u, s);
            mbar_arrive_remote(peer + OFF_MB * 4u + 8u * buf);
            mbar_wait_acq(sbase + OFF_MB * 4u + 8u * buf, (uint32_t)((it >> 1) & 1));
            sm[OFF_RT + t] = s + sm[OFF_REM + buf * 128 + t] - sm[OFF_B + t];
        }
        __syncthreads();                                   // bar3: rt ready

        // --- u = C * rt (t<256, 2/row), then split u to fp16 hi/lo ---
        if (t < 256) {
            int i = t >> 1, h = t & 1, base = i & 15;
            float accu = 0.0f;
#pragma unroll
            for (int m = 0; m < 16; m++) {
                int j = 8 * ((base + m) & 15) + 4 * h;
                float4 c4 = *(const float4*)(sm + OFF_C + i * 128 + j);
                float4 r4 = *(const float4*)(sm + OFF_RT + j);
                accu += c4.x * r4.x + c4.y * r4.y + c4.z * r4.z + c4.w * r4.w;
            }
            accu += __shfl_xor_sync(0xffffffffu, accu, 1); // both lanes hold u_i
            float un = __shfl_down_sync(0xffffffffu, accu, 2);   // u_{i+1}
            if ((t & 3) == 0) {
                __half2 hu = __floats2half2_rn(accu, un);
                float2 fu = __half22float2(hu);
                __half2 lu = __floats2half2_rn(accu - fu.x, un - fu.y);
                ((uint32_t*)(sm + OFF_UH))[t >> 2] = *(uint32_t*)&hu;
                ((uint32_t*)(sm + OFF_UL))[t >> 2] = *(uint32_t*)&lu;
            }
        }
        __syncthreads();                                   // bar4: u ready

        // --- pass 2 (HMMA, ldmatrix.trans): corr = A^T * u ---
        {
            const uint32_t* uh = (const uint32_t*)(sm + OFF_UH);
            const uint32_t* ul = (const uint32_t*)(sm + OFF_UL);
#pragma unroll
            for (int mi = 0; mi < 2; mi++) {
                int mt = 2 * w + mi, cc0 = mt * 16;
                float d0 = 0.f, d1 = 0.f, d2 = 0.f, d3 = 0.f;
                uint32_t addr = aA + p2_rowoff + (uint32_t)(cc0 * 2);
#pragma unroll
                for (int kt = 0; kt < 8; kt++) {
                    uint32_t a0, a1, a2, a3;
                    ldsm_x4t(a0, a1, a2, a3, addr);
                    addr += 16u * 1040u;                    // +16 rows
                    int kb = kt * 8 + bc;
                    mma16816(d0, d1, d2, d3, a0, a1, a2, a3, uh[kb], uh[kb + 4]);
                    mma16816(d0, d1, d2, d3, a0, a1, a2, a3, ul[kb], ul[kb + 4]);
                }
                if ((l & 3) == 0) {
                    sm[OFF_CORR + cc0 + (l >> 2)]     = d0;
                    sm[OFF_CORR + cc0 + 8 + (l >> 2)] = d2;
                }
            }
        }
        __syncthreads();                                   // bar5: corr ready

        // --- epilogue: z' = x_half - corr, x_new = y - corr ---
        if (t < 256) {
            float2 cr = *(const float2*)(sm + OFF_CORR + 2 * t);
            z2.x = xh2.x - cr.x; z2.y = xh2.y - cr.y;
            yv2.x -= cr.x; yv2.y -= cr.y;                  // x_new
        }
    }

    if (t < 256)
        ((float2*)(out + (size_t)b * NN + rank * 512))[t] = yv2;
    cluster_sync_();
}

// --------------------------------------------------------------------------
extern "C" void kernel_launch(void* const* d_in, const int* in_sizes, int n_in,
                              void* d_out, int out_size) {
    const float* A  = (const float*)d_in[0];
    const float* bv = (const float*)d_in[1];
    const float* D1 = (const float*)d_in[2];
    const float* D2 = (const float*)d_in[3];
    float* out = (float*)d_out;

    cudaFuncSetAttribute(k_inv,  cudaFuncAttributeMaxDynamicSharedMemorySize, 66052);
    cudaFuncSetAttribute(k_iter, cudaFuncAttributeMaxDynamicSharedMemorySize, SMEM_WORDS * 4);

    k_convert<<<32768, 256>>>(A);
    k_aat<<<BSZ, 256>>>();
    k_inv<<<BSZ, 512, 66052>>>();
    k_iter<<<BSZ * 2, 512, SMEM_WORDS * 4>>>(bv, D1, D2, out);
}

// round 12
// speedup vs baseline: 1.3813x; 1.0005x over previous
#include <cuda_runtime.h>
#include <cuda_fp16.h>
#include <cstdint>

#define BSZ   256
#define MM    128
#define NN    1024
#define ITERS 100
#define ALPHA 0.1f

__device__ __half g_Ah[(size_t)BSZ * MM * NN];
__device__ float  g_C [(size_t)BSZ * MM * MM];   // AAT -> inverse (in place)

__device__ __forceinline__ uint32_t smem_u32(const void* p) {
    uint32_t a;
    asm("{ .reg .u64 t; cvta.to.shared.u64 t, %1; cvt.u32.u64 %0, t; }" : "=r"(a) : "l"(p));
    return a;
}
__device__ __forceinline__ uint32_t mapa_rank(uint32_t addr, uint32_t trank) {
    uint32_t r;
    asm("mapa.shared::cluster.u32 %0, %1, %2;" : "=r"(r) : "r"(addr), "r"(trank));
    return r;
}
__device__ __forceinline__ void cluster_sync_() {
    asm volatile("barrier.cluster.arrive.aligned;" ::: "memory");
    asm volatile("barrier.cluster.wait.aligned;"   ::: "memory");
}
__device__ __forceinline__ void st_cluster_f32(uint32_t addr, float v) {
    asm volatile("st.shared::cluster.f32 [%0], %1;" :: "r"(addr), "f"(v) : "memory");
}
__device__ __forceinline__ void mbar_init(uint32_t a, uint32_t c) {
    asm volatile("mbarrier.init.shared.b64 [%0], %1;" :: "r"(a), "r"(c) : "memory");
}
__device__ __forceinline__ void mbar_arrive_remote(uint32_t ra) {
    asm volatile("mbarrier.arrive.release.cluster.shared::cluster.b64 _, [%0];" :: "r"(ra) : "memory");
}
__device__ __forceinline__ void mbar_wait_acq(uint32_t mb, uint32_t par) {
    asm volatile(
        "{\n\t.reg .pred P;\n\t"
        "WL%=:\n\t"
        "mbarrier.try_wait.parity.acquire.cluster.shared::cta.b64 P, [%0], %1, 0x989680;\n\t"
        "@P bra.uni WD%=;\n\t"
        "bra.uni WL%=;\n\t"
        "WD%=:\n\t}" :: "r"(mb), "r"(par) : "memory");
}
__device__ __forceinline__ void ldsm_x4(uint32_t& a0, uint32_t& a1, uint32_t& a2, uint32_t& a3, uint32_t addr) {
    asm volatile("ldmatrix.sync.aligned.m8n8.x4.shared.b16 {%0,%1,%2,%3}, [%4];"
                 : "=r"(a0), "=r"(a1), "=r"(a2), "=r"(a3) : "r"(addr));
}
__device__ __forceinline__ void ldsm_x4t(uint32_t& a0, uint32_t& a1, uint32_t& a2, uint32_t& a3, uint32_t addr) {
    asm volatile("ldmatrix.sync.aligned.m8n8.x4.trans.shared.b16 {%0,%1,%2,%3}, [%4];"
                 : "=r"(a0), "=r"(a1), "=r"(a2), "=r"(a3) : "r"(addr));
}
__device__ __forceinline__ void mma16816(float& c0, float& c1, float& c2, float& c3,
                                         uint32_t a0, uint32_t a1, uint32_t a2, uint32_t a3,
                                         uint32_t b0, uint32_t b1) {
    asm volatile("mma.sync.aligned.m16n8k16.row.col.f32.f16.f16.f32 "
                 "{%0,%1,%2,%3},{%4,%5,%6,%7},{%8,%9},{%0,%1,%2,%3};"
                 : "+f"(c0), "+f"(c1), "+f"(c2), "+f"(c3)
                 : "r"(a0), "r"(a1), "r"(a2), "r"(a3), "r"(b0), "r"(b1));
}

// --------------------------------------------------------------------------
__global__ void k_convert(const float* __restrict__ A) {
    size_t i = ((size_t)blockIdx.x * blockDim.x + threadIdx.x) * 4;
    float4 v = *(const float4*)(A + i);
    __half2* dst = (__half2*)(g_Ah + i);
    dst[0] = __floats2half2_rn(v.x, v.y);
    dst[1] = __floats2half2_rn(v.z, v.w);
}

// k_aat (HMMA, verified R9) --------------------------------------------------
#define AT_PITCH_B 272
__global__ void __launch_bounds__(256) k_aat() {
    __shared__ __half tile[128 * (AT_PITCH_B / 2)];
    const int b = blockIdx.x, t = threadIdx.x, w = t >> 5, l = t & 31;
    const __half* Ab = g_Ah + (size_t)b * MM * NN;
    const uint32_t tbase = smem_u32(tile);

    float acc[16][4];
#pragma unroll
    for (int nt = 0; nt < 16; nt++)
#pragma unroll
        for (int q = 0; q < 4; q++) acc[nt][q] = 0.0f;

    const int m0 = w * 16;
    const uint32_t aAddr = tbase + (uint32_t)(m0 + (l & 15)) * AT_PITCH_B
                         + (uint32_t)((l >> 4) << 4);
    const int bg = l >> 3;
    const uint32_t bAddr0 = tbase + (uint32_t)((l & 7) + ((bg >> 1) << 3)) * AT_PITCH_B
                          + (uint32_t)((bg & 1) << 4);

    for (int kc = 0; kc < 8; kc++) {
#pragma unroll
        for (int q = 0; q < 8; q++) {
            int i = t + 256 * q, r = i >> 4, c4 = i & 15;
            *(uint4*)((char*)tile + r * AT_PITCH_B + c4 * 16) =
                *(const uint4*)(Ab + (size_t)r * NN + kc * 128 + c4 * 8);
        }
        __syncthreads();

#pragma unroll
        for (int kt = 0; kt < 8; kt++) {
            uint32_t a0, a1, a2, a3;
            ldsm_x4(a0, a1, a2, a3, aAddr + (uint32_t)(kt * 32));
#pragma unroll
            for (int nt = 0; nt < 16; nt += 2) {
                uint32_t r0, r1, r2, r3;
                ldsm_x4(r0, r1, r2, r3,
                        bAddr0 + (uint32_t)(nt * 8) * AT_PITCH_B + (uint32_t)(kt * 32));
                mma16816(acc[nt][0],   acc[nt][1],   acc[nt][2],   acc[nt][3],
                         a0, a1, a2, a3, r0, r1);
                mma16816(acc[nt+1][0], acc[nt+1][1], acc[nt+1][2], acc[nt+1][3],
                         a0, a1, a2, a3, r2, r3);
            }
        }
        __syncthreads();
    }

    float* Cb = g_C + (size_t)b * MM * MM;
    const int r0 = m0 + (l >> 2), c0 = 2 * (l & 3);
#pragma unroll
    for (int nt = 0; nt < 16; nt++) {
        *(float2*)&Cb[(size_t)r0 * MM + nt * 8 + c0]       = make_float2(acc[nt][0], acc[nt][1]);
        *(float2*)&Cb[(size_t)(r0 + 8) * MM + nt * 8 + c0] = make_float2(acc[nt][2], acc[nt][3]);
    }
}

// Gauss-Jordan inverse, 512 threads (verified R10 setup win) -----------------
__global__ void __launch_bounds__(512) k_inv() {
    extern __shared__ float sm[];
    float* sM = sm; float* sf = sm + 16384; float* sp = sm + 16512;
    int b = blockIdx.x, t = threadIdx.x;
    float* Cb = g_C + (size_t)b * MM * MM;
    for (int i = t; i < 4096; i += 512) ((float4*)sM)[i] = ((const float4*)Cb)[i];
    __syncthreads();
    for (int k = 0; k < 128; k++) {
        if (t == 0) sp[0] = 1.0f / sM[k * 128 + k];
        __syncthreads();
        float ipiv = sp[0];
        if (t < 128) {
            float v = sM[k * 128 + t];
            sM[k * 128 + t] = (t == k) ? ipiv : v * ipiv;
            sf[t] = (t == k) ? 0.0f : sM[t * 128 + k];
        }
        __syncthreads();
        int j = t & 127, g = t >> 7;
        float mk = sM[k * 128 + j];
#pragma unroll 4
        for (int ii = 0; ii < 32; ii++) {
            int i = g * 32 + ii;
            if (i == k) continue;
            float fi = sf[i];
            float v = sM[i * 128 + j];
            sM[i * 128 + j] = (j == k) ? (-fi * mk) : (v - fi * mk);
        }
        __syncthreads();
    }
    for (int i = t; i < 4096; i += 512) ((float4*)Cb)[i] = ((const float4*)sM)[i];
}

// Iterations: R6/R9 core, ONE change: split hi/lo HMMA accumulators ----------
#define APAD_U4  65
#define OFF_C    0                     // 16384 f
#define OFF_A    16384                 // 33280 w (128*260 u32)
#define OFF_YH   49664                 // 256 u32 (half2 y_hi)
#define OFF_YL   49920                 // 256 u32
#define OFF_B    50176                 // 128 f
#define OFF_SR0  50304                 // 128 f (khalf 0 partial)
#define OFF_SR1  50432                 // 128 f (khalf 1 partial)
#define OFF_REM  50560                 // 256 f (peer partial, 2 bufs)
#define OFF_RT   50816                 // 128 f
#define OFF_UH   50944                 // 64 u32 (half2 u_hi)
#define OFF_UL   51008                 // 64 u32
#define OFF_CORR 51072                 // 512 f
#define OFF_MB   51584                 // 2 x u64 mbarriers
#define SMEM_WORDS 51588               // 206352 bytes

__global__ void __launch_bounds__(512, 1) __cluster_dims__(2, 1, 1)
k_iter(const float* __restrict__ bvec, const float* __restrict__ D1,
       const float* __restrict__ D2, float* __restrict__ out) {
    extern __shared__ float sm[];
    const int t = threadIdx.x, w = t >> 5, l = t & 31;
    const int b = blockIdx.x >> 1;
    const uint32_t rank = blockIdx.x & 1;
    const uint32_t sbase = smem_u32(sm);
    const uint32_t peer = mapa_rank(sbase, rank ^ 1u);
    const uint32_t aA = sbase + OFF_A * 4u;

    {   // load C, padded A-half, b
        float4* d = (float4*)(sm + OFF_C);
        const float4* s = (const float4*)(g_C + (size_t)b * MM * MM);
#pragma unroll
        for (int q = 0; q < 8; q++) d[t + 512 * q] = s[t + 512 * q];
        uint4* da = (uint4*)(sm + OFF_A);
        const uint4* sa = (const uint4*)(g_Ah + (size_t)b * MM * NN + (size_t)rank * 512);
#pragma unroll
        for (int q = 0; q < 16; q++) {
            int i = t + 512 * q, r = i >> 6, c4 = i & 63;
            da[r * APAD_U4 + c4] = sa[(size_t)r * 128 + c4];
        }
        if (t < 128) sm[OFF_B + t] = bvec[(size_t)b * MM + t];
        if (t == 0) {
            mbar_init(sbase + OFF_MB * 4u, 128);
            mbar_init(sbase + OFF_MB * 4u + 8u, 128);
        }
    }

    // per-thread state: t<256 owns local cols 2t, 2t+1
    float2 thr2 = make_float2(0.f, 0.f), dv2 = make_float2(0.f, 0.f);
    float2 z2 = make_float2(0.f, 0.f), xh2, yv2 = make_float2(0.f, 0.f);
    if (t < 256) {
        float2 d1 = ((const float2*)(D1 + (size_t)b * NN + rank * 512))[t];
        float2 d2 = ((const float2*)(D2 + (size_t)b * NN + rank * 512))[t];
        thr2.x = ALPHA * fabsf(d1.x); thr2.y = ALPHA * fabsf(d1.y);
        dv2.x = 1.0f / (1.0f + 2.0f * ALPHA * d2.x * d2.x);
        dv2.y = 1.0f / (1.0f + 2.0f * ALPHA * d2.y * d2.y);
    }
    __syncthreads();
    cluster_sync_();

    // pass1 per-warp constants: warp w -> m-tile rows 16*(w&7), k-half w>>3
    const int p1_m0 = (w & 7) * 16, p1_kh = w >> 3;
    const uint32_t p1_addr = aA + (uint32_t)(p1_m0 + (l & 15)) * 1040u
                           + (uint32_t)(p1_kh * 512) + (uint32_t)((l >> 4) << 4);
    const int bc = l & 3;              // tid%4: b-frag k-subgroup
    // pass2: warp w -> m-tiles (cols) 2w, 2w+1
    const uint32_t p2_rowoff = (uint32_t)((l & 7) + ((l >> 4) << 3)) * 1040u
                             + (uint32_t)((l & 8) << 1);

    for (int it = 0; it < ITERS; it++) {
        const int buf = it & 1;
        // --- elementwise: soft-threshold, y = 2x_half - z, split to fp16 hi/lo
        if (t < 256) {
            float a0 = z2.x - thr2.x, c0 = z2.x + thr2.x;
            float a1 = z2.y - thr2.y, c1 = z2.y + thr2.y;
            xh2.x = (a0 > 0.f) ? a0 * dv2.x : ((c0 < 0.f) ? c0 * dv2.x : 0.f);
            xh2.y = (a1 > 0.f) ? a1 * dv2.y : ((c1 < 0.f) ? c1 * dv2.y : 0.f);
            yv2.x = 2.0f * xh2.x - z2.x;
            yv2.y = 2.0f * xh2.y - z2.y;
            __half2 hy = __floats2half2_rn(yv2.x, yv2.y);
            float2 fy = __half22float2(hy);
            __half2 ly = __floats2half2_rn(yv2.x - fy.x, yv2.y - fy.y);
            ((uint32_t*)(sm + OFF_YH))[t] = *(uint32_t*)&hy;
            ((uint32_t*)(sm + OFF_YL))[t] = *(uint32_t*)&ly;
        }
        __syncthreads();                                   // bar1: y ready

        // --- pass 1 (HMMA, SPLIT hi/lo accumulators) ---
        {
            float ch0 = 0.f, ch1 = 0.f, ch2 = 0.f, ch3 = 0.f;
            float cl0 = 0.f, cl1 = 0.f, cl2 = 0.f, cl3 = 0.f;
            const uint32_t* yh = (const uint32_t*)(sm + OFF_YH) + p1_kh * 128;
            const uint32_t* yl = (const uint32_t*)(sm + OFF_YL) + p1_kh * 128;
            uint32_t addr = p1_addr;
#pragma unroll
            for (int kt = 0; kt < 16; kt++) {
                uint32_t a0, a1, a2, a3;
                ldsm_x4(a0, a1, a2, a3, addr);
                addr += 32u;                                // +16 halves
                int kb = kt * 8 + bc;
                mma16816(ch0, ch1, ch2, ch3, a0, a1, a2, a3, yh[kb], yh[kb + 4]);
                mma16816(cl0, cl1, cl2, cl3, a0, a1, a2, a3, yl[kb], yl[kb + 4]);
            }
            if ((l & 3) == 0) {
                float* srp = sm + (p1_kh ? OFF_SR1 : OFF_SR0);
                srp[p1_m0 + (l >> 2)]     = ch0 + cl0;
                srp[p1_m0 + 8 + (l >> 2)] = ch2 + cl2;
            }
        }
        __syncthreads();                                   // bar2: partials ready

        // --- exchange + r_total (t<128) ---
        if (t < 128) {
            float s = sm[OFF_SR0 + t] + sm[OFF_SR1 + t];
            st_cluster_f32(peer + (uint32_t)(OFF_REM + buf * 128 + t) * 4u, s);
            mbar_arrive_remote(peer + OFF_MB * 4u + 8u * buf);
            mbar_wait_acq(sbase + OFF_MB * 4u + 8u * buf, (uint32_t)((it >> 1) & 1));
            sm[OFF_RT + t] = s + sm[OFF_REM + buf * 128 + t] - sm[OFF_B + t];
        }
        __syncthreads();                                   // bar3: rt ready

        // --- u = C * rt (t<256, 2/row), then split u to fp16 hi/lo ---
        if (t < 256) {
            int i = t >> 1, h = t & 1, base = i & 15;
            float accu = 0.0f;
#pragma unroll
            for (int m = 0; m < 16; m++) {
                int j = 8 * ((base + m) & 15) + 4 * h;
                float4 c4 = *(const float4*)(sm + OFF_C + i * 128 + j);
                float4 r4 = *(const float4*)(sm + OFF_RT + j);
                accu += c4.x * r4.x + c4.y * r4.y + c4.z * r4.z + c4.w * r4.w;
            }
            accu += __shfl_xor_sync(0xffffffffu, accu, 1); // both lanes hold u_i
            float un = __shfl_down_sync(0xffffffffu, accu, 2);   // u_{i+1}
            if ((t & 3) == 0) {
                __half2 hu = __floats2half2_rn(accu, un);
                float2 fu = __half22float2(hu);
                __half2 lu = __floats2half2_rn(accu - fu.x, un - fu.y);
                ((uint32_t*)(sm + OFF_UH))[t >> 2] = *(uint32_t*)&hu;
                ((uint32_t*)(sm + OFF_UL))[t >> 2] = *(uint32_t*)&lu;
            }
        }
        __syncthreads();                                   // bar4: u ready

        // --- pass 2 (HMMA trans, SPLIT hi/lo accumulators) ---
        {
            const uint32_t* uh = (const uint32_t*)(sm + OFF_UH);
            const uint32_t* ul = (const uint32_t*)(sm + OFF_UL);
#pragma unroll
            for (int mi = 0; mi < 2; mi++) {
                int mt = 2 * w + mi, cc0 = mt * 16;
                float dh0 = 0.f, dh1 = 0.f, dh2 = 0.f, dh3 = 0.f;
                float dl0 = 0.f, dl1 = 0.f, dl2 = 0.f, dl3 = 0.f;
                uint32_t addr = aA + p2_rowoff + (uint32_t)(cc0 * 2);
#pragma unroll
                for (int kt = 0; kt < 8; kt++) {
                    uint32_t a0, a1, a2, a3;
                    ldsm_x4t(a0, a1, a2, a3, addr);
                    addr += 16u * 1040u;                    // +16 rows
                    int kb = kt * 8 + bc;
                    mma16816(dh0, dh1, dh2, dh3, a0, a1, a2, a3, uh[kb], uh[kb + 4]);
                    mma16816(dl0, dl1, dl2, dl3, a0, a1, a2, a3, ul[kb], ul[kb + 4]);
                }
                if ((l & 3) == 0) {
                    sm[OFF_CORR + cc0 + (l >> 2)]     = dh0 + dl0;
                    sm[OFF_CORR + cc0 + 8 + (l >> 2)] = dh2 + dl2;
                }
            }
        }
        __syncthreads();                                   // bar5: corr ready

        // --- epilogue: z' = x_half - corr, x_new = y - corr ---
        if (t < 256) {
            float2 cr = *(const float2*)(sm + OFF_CORR + 2 * t);
            z2.x = xh2.x - cr.x; z2.y = xh2.y - cr.y;
            yv2.x -= cr.x; yv2.y -= cr.y;                  // x_new
        }
    }

    if (t < 256)
        ((float2*)(out + (size_t)b * NN + rank * 512))[t] = yv2;
    cluster_sync_();
}

// --------------------------------------------------------------------------
extern "C" void kernel_launch(void* const* d_in, const int* in_sizes, int n_in,
                              void* d_out, int out_size) {
    const float* A  = (const float*)d_in[0];
    const float* bv = (const float*)d_in[1];
    const float* D1 = (const float*)d_in[2];
    const float* D2 = (const float*)d_in[3];
    float* out = (float*)d_out;

    cudaFuncSetAttribute(k_inv,  cudaFuncAttributeMaxDynamicSharedMemorySize, 66052);
    cudaFuncSetAttribute(k_iter, cudaFuncAttributeMaxDynamicSharedMemorySize, SMEM_WORDS * 4);

    k_convert<<<32768, 256>>>(A);
    k_aat<<<BSZ, 256>>>();
    k_inv<<<BSZ, 512, 66052>>>();
    k_iter<<<BSZ * 2, 512, SMEM_WORDS * 4>>>(bv, D1, D2, out);
}